// round 2
// baseline (speedup 1.0000x reference)
#include <cuda_runtime.h>
#include <math.h>

#define N_NODES 10000
#define C_IN 128
#define D_OUT 20
#define KNN_K 16
#define SPLIT 4
#define CAND_PER (N_NODES / SPLIT)   // 2500
#define QB 128                        // queries per block == threads per block
#define TC 128                        // candidate tile size

// ---------------- scratch (static device globals; no allocs) ----------------
__device__ float g_h[N_NODES * D_OUT];
__device__ float g_emb[N_NODES * D_OUT];
__device__ float g_embn[N_NODES * D_OUT];
__device__ float g_sqe[N_NODES];
__device__ float g_sqp[N_NODES];
__device__ float g_mu[D_OUT];
__device__ float g_rinv[D_OUT];
__device__ float g_part_d[N_NODES * SPLIT * KNN_K];
__device__ int   g_part_i[N_NODES * SPLIT * KNN_K];
__device__ int   g_idx_emb[N_NODES * KNN_K];
__device__ int   g_idx_pos[N_NODES * KNN_K];

__device__ __forceinline__ float inf_f() { return __int_as_float(0x7f800000); }

// ---------------- 1) linear: h = x @ W + b ----------------
__global__ void k_linear(const float* __restrict__ x, const float* __restrict__ W,
                         const float* __restrict__ b) {
    int t = blockIdx.x * blockDim.x + threadIdx.x;
    if (t >= N_NODES * D_OUT) return;
    int i = t / D_OUT;
    int d = t % D_OUT;
    const float* xr = x + (size_t)i * C_IN;
    float acc = 0.f;
#pragma unroll 8
    for (int c = 0; c < C_IN; ++c) acc = fmaf(xr[c], W[c * D_OUT + d], acc);
    g_h[t] = acc + b[d];
}

// ---------------- 2) batchnorm stats (deterministic) ----------------
__global__ void k_stats() {
    __shared__ float ss[256];
    __shared__ float sq[256];
    int d = blockIdx.x;
    int tid = threadIdx.x;
    float s = 0.f, q = 0.f;
    for (int i = tid; i < N_NODES; i += 256) {
        float v = g_h[i * D_OUT + d];
        s += v;
        q = fmaf(v, v, q);
    }
    ss[tid] = s; sq[tid] = q;
    __syncthreads();
    for (int o = 128; o > 0; o >>= 1) {
        if (tid < o) { ss[tid] += ss[tid + o]; sq[tid] += sq[tid + o]; }
        __syncthreads();
    }
    if (tid == 0) {
        float mu = ss[0] / (float)N_NODES;
        float var = sq[0] / (float)N_NODES - mu * mu;
        g_mu[d] = mu;
        g_rinv[d] = 1.f / sqrtf(var + 1e-5f);
    }
}

// ---------------- 3) emb = relu(bn(h)); embn = emb + noise*1e-4 ----------------
__global__ void k_emb(const float* __restrict__ noise, const float* __restrict__ gamma,
                      const float* __restrict__ beta) {
    int t = blockIdx.x * blockDim.x + threadIdx.x;
    if (t >= N_NODES * D_OUT) return;
    int d = t % D_OUT;
    float e = (g_h[t] - g_mu[d]) * g_rinv[d] * gamma[d] + beta[d];
    e = fmaxf(e, 0.f);
    g_emb[t] = e;
    g_embn[t] = e + noise[t] * 1e-4f;
}

// ---------------- 4) row squared norms (emb and pos) ----------------
// pos squared-norm mimics jnp.sum(pos*pos, axis=1): separately-rounded squares,
// left-to-right reduction, NO fma contraction.
__global__ void k_sqn(const float* __restrict__ pos) {
    int i = blockIdx.x * blockDim.x + threadIdx.x;
    if (i >= N_NODES) return;
    float s = 0.f;
#pragma unroll
    for (int d = 0; d < D_OUT; ++d) {
        float v = g_emb[i * D_OUT + d];
        s = fmaf(v, v, s);
    }
    g_sqe[i] = s;
    float p0 = pos[i * 3 + 0], p1 = pos[i * 3 + 1], p2 = pos[i * 3 + 2];
    float s0 = __fmul_rn(p0, p0);
    float s1 = __fmul_rn(p1, p1);
    float s2 = __fmul_rn(p2, p2);
    g_sqp[i] = __fadd_rn(__fadd_rn(s0, s1), s2);
}

// ---------------- top-k insertion (sorted ascending by (d2, idx)) ----------------
__device__ __forceinline__ bool lt_pair(float d2a, int ia, float d2b, int ib) {
    return (d2a < d2b) || (d2a == d2b && ia < ib);
}

__device__ __forceinline__ void topk_insert(float (&kd)[KNN_K], int (&ki)[KNN_K],
                                            float d2, int j) {
    if (lt_pair(d2, j, kd[KNN_K - 1], ki[KNN_K - 1])) {
        kd[KNN_K - 1] = d2;
        ki[KNN_K - 1] = j;
#pragma unroll
        for (int s = KNN_K - 1; s > 0; --s) {
            if (lt_pair(kd[s], ki[s], kd[s - 1], ki[s - 1])) {
                float td = kd[s]; kd[s] = kd[s - 1]; kd[s - 1] = td;
                int   ti = ki[s]; ki[s] = ki[s - 1]; ki[s - 1] = ti;
            }
        }
    }
}

// d2 composition. For the pos path (DIMS==3) mimic the reference expansion
// bit-for-bit:  fl( fl(sq_i + sq_j) - fl(2*dot) )  — 2*dot is exact, the
// subtraction is a separately-rounded add (NOT fused).
// For the emb path (DIMS==20) keep the round-1 arithmetic, which already
// matched the reference exactly.
template <int DIMS>
__device__ __forceinline__ float compose_d2(float qsq, float ssq, float dot) {
    if (DIMS == 3) {
        float s = __fadd_rn(qsq, ssq);
        return __fadd_rn(s, -__fmul_rn(2.f, dot));
    } else {
        return fmaf(-2.f, dot, qsq + ssq);
    }
}

// ---------------- 5) brute-force knn over a candidate split ----------------
template <int DIMS>
__global__ void __launch_bounds__(QB) k_knn(const float* __restrict__ feat,
                                            const float* __restrict__ sqn) {
    __shared__ float s_feat[TC * DIMS];
    __shared__ float s_sq[TC];

    const int tid = threadIdx.x;
    const int q = blockIdx.x * QB + tid;
    const int split = blockIdx.y;
    const int cbeg = split * CAND_PER;
    const int cend = cbeg + CAND_PER;
    const bool valid = (q < N_NODES);

    float qv[DIMS];
    float qsq = 0.f;
    if (valid) {
        qsq = sqn[q];
#pragma unroll
        for (int d = 0; d < DIMS; ++d) qv[d] = feat[(size_t)q * DIMS + d];
    }

    float kd[KNN_K];
    int ki[KNN_K];
#pragma unroll
    for (int r = 0; r < KNN_K; ++r) { kd[r] = inf_f(); ki[r] = 0x7fffffff; }

    for (int base = cbeg; base < cend; base += TC) {
        int count = min(TC, cend - base);
        __syncthreads();
        for (int idx = tid; idx < count * DIMS; idx += QB)
            s_feat[idx] = feat[(size_t)base * DIMS + idx];
        if (tid < count) s_sq[tid] = sqn[base + tid];
        __syncthreads();

        if (valid) {
            int c = 0;
            for (; c + 4 <= count; c += 4) {
                float a0 = 0.f, a1 = 0.f, a2 = 0.f, a3 = 0.f;
#pragma unroll
                for (int kk = 0; kk < DIMS; ++kk) {
                    float qk = qv[kk];
                    a0 = fmaf(qk, s_feat[(c + 0) * DIMS + kk], a0);
                    a1 = fmaf(qk, s_feat[(c + 1) * DIMS + kk], a1);
                    a2 = fmaf(qk, s_feat[(c + 2) * DIMS + kk], a2);
                    a3 = fmaf(qk, s_feat[(c + 3) * DIMS + kk], a3);
                }
                int j0 = base + c;
                if (j0 + 0 != q) topk_insert(kd, ki, compose_d2<DIMS>(qsq, s_sq[c + 0], a0), j0 + 0);
                if (j0 + 1 != q) topk_insert(kd, ki, compose_d2<DIMS>(qsq, s_sq[c + 1], a1), j0 + 1);
                if (j0 + 2 != q) topk_insert(kd, ki, compose_d2<DIMS>(qsq, s_sq[c + 2], a2), j0 + 2);
                if (j0 + 3 != q) topk_insert(kd, ki, compose_d2<DIMS>(qsq, s_sq[c + 3], a3), j0 + 3);
            }
            for (; c < count; ++c) {
                float a = 0.f;
#pragma unroll
                for (int kk = 0; kk < DIMS; ++kk)
                    a = fmaf(qv[kk], s_feat[c * DIMS + kk], a);
                int j = base + c;
                if (j != q) topk_insert(kd, ki, compose_d2<DIMS>(qsq, s_sq[c], a), j);
            }
        }
    }

    if (valid) {
        size_t o = ((size_t)q * SPLIT + split) * KNN_K;
#pragma unroll
        for (int r = 0; r < KNN_K; ++r) {
            g_part_d[o + r] = kd[r];
            g_part_i[o + r] = ki[r];
        }
    }
}

// ---------------- 6) merge SPLIT sorted partial lists per query ----------------
__global__ void k_merge(int* __restrict__ out_idx) {
    int q = blockIdx.x * blockDim.x + threadIdx.x;
    if (q >= N_NODES) return;
    int ptr[SPLIT];
#pragma unroll
    for (int s = 0; s < SPLIT; ++s) ptr[s] = 0;
    const float* d = g_part_d + (size_t)q * SPLIT * KNN_K;
    const int* ii = g_part_i + (size_t)q * SPLIT * KNN_K;
    for (int r = 0; r < KNN_K; ++r) {
        float bd = inf_f();
        int bi = 0x7fffffff;
        int bs = 0;
#pragma unroll
        for (int s = 0; s < SPLIT; ++s) {
            float dv = d[s * KNN_K + ptr[s]];
            int iv = ii[s * KNN_K + ptr[s]];
            if (lt_pair(dv, iv, bd, bi)) { bd = dv; bi = iv; bs = s; }
        }
        out_idx[q * KNN_K + r] = bi;
        ptr[bs]++;
    }
}

// ---------------- 7) epilogue: p, soft_index_v, edges_large, edge_index ----------------
__global__ void k_final(const float* __restrict__ tptr, float* __restrict__ out) {
    const int NK = N_NODES * KNN_K;
    int e = blockIdx.x * blockDim.x + threadIdx.x;
    if (e >= NK) return;
    int i = e / KNN_K;
    int src = g_idx_emb[e];
    float s = 0.f;
#pragma unroll
    for (int d = 0; d < D_OUT; ++d) {
        float df = g_embn[src * D_OUT + d] - g_embn[i * D_OUT + d];
        s = fmaf(df, df, s);
    }
    float dist = sqrtf(s);
    float p = expf(-tptr[0] * dist);
    float fi = (float)i;
    float fs = (float)src;

    out[e] = p;                               // p
    out[NK + e] = p;                          // soft_index_v row 0
    out[2 * NK + e] = fi;                     // soft_index_v row 1 (dst)
    out[3 * NK + e] = fs;                     // edges_large row 0 (src)
    out[4 * NK + e] = fi;                     // edges_large row 1 (dst)
    out[5 * NK + e] = fs;                     // edge_index row 0, emb part
    out[6 * NK + e] = (float)g_idx_pos[e];    // edge_index row 0, pos part
    out[7 * NK + e] = fi;                     // edge_index row 1, emb part
    out[8 * NK + e] = fi;                     // edge_index row 1, pos part
}

// ---------------- launch ----------------
extern "C" void kernel_launch(void* const* d_in, const int* in_sizes, int n_in,
                              void* d_out, int out_size) {
    const float* x     = (const float*)d_in[0];
    const float* pos   = (const float*)d_in[1];
    const float* noise = (const float*)d_in[2];
    const float* W     = (const float*)d_in[3];
    const float* b     = (const float*)d_in[4];
    const float* gamma = (const float*)d_in[5];
    const float* beta  = (const float*)d_in[6];
    const float* t     = (const float*)d_in[7];
    float* out = (float*)d_out;

    int nd = N_NODES * D_OUT;
    k_linear<<<(nd + 255) / 256, 256>>>(x, W, b);
    k_stats<<<D_OUT, 256>>>();
    k_emb<<<(nd + 255) / 256, 256>>>(noise, gamma, beta);
    k_sqn<<<(N_NODES + 255) / 256, 256>>>(pos);

    int* d_idx_emb; cudaGetSymbolAddress((void**)&d_idx_emb, g_idx_emb);
    int* d_idx_pos; cudaGetSymbolAddress((void**)&d_idx_pos, g_idx_pos);
    float* d_emb;   cudaGetSymbolAddress((void**)&d_emb, g_emb);
    float* d_sqe;   cudaGetSymbolAddress((void**)&d_sqe, g_sqe);
    float* d_sqp;   cudaGetSymbolAddress((void**)&d_sqp, g_sqp);

    dim3 kgrid((N_NODES + QB - 1) / QB, SPLIT);

    // embedding knn
    k_knn<D_OUT><<<kgrid, QB>>>(d_emb, d_sqe);
    k_merge<<<(N_NODES + 255) / 256, 256>>>(d_idx_emb);

    // pos knn
    k_knn<3><<<kgrid, QB>>>(pos, d_sqp);
    k_merge<<<(N_NODES + 255) / 256, 256>>>(d_idx_pos);

    const int NK = N_NODES * KNN_K;
    k_final<<<(NK + 255) / 256, 256>>>(t, out);
    (void)in_sizes; (void)n_in; (void)out_size;
}

// round 3
// speedup vs baseline: 2.4130x; 2.4130x over previous
#include <cuda_runtime.h>
#include <math.h>

#define N_NODES 10000
#define C_IN 128
#define D_OUT 20
#define KNN_K 16
#define FULLM 0xffffffffu

#define KNN_TPB 512        // threads per knn block
#define WARPS_PB (KNN_TPB / 32)   // 16 queries per block
#define TC 512             // candidate tile
#define EPAD 22            // emb smem row stride (floats) -> conflict-free float2

// ---------------- scratch (static device globals; no allocs) ----------------
__device__ float g_h[N_NODES * D_OUT];
__device__ float g_emb[N_NODES * D_OUT];
__device__ float g_embn[N_NODES * D_OUT];
__device__ float g_sqe[N_NODES];
__device__ float4 g_pos4[N_NODES];         // {x, y, z, sq}
__device__ float g_mu[D_OUT];
__device__ float g_rinv[D_OUT];
__device__ int   g_idx_emb[N_NODES * KNN_K];
__device__ int   g_idx_pos[N_NODES * KNN_K];

__device__ __forceinline__ float inf_f() { return __int_as_float(0x7f800000); }

// ---------------- 1) linear: h = x @ W + b ----------------
__global__ void k_linear(const float* __restrict__ x, const float* __restrict__ W,
                         const float* __restrict__ b) {
    int t = blockIdx.x * blockDim.x + threadIdx.x;
    if (t >= N_NODES * D_OUT) return;
    int i = t / D_OUT;
    int d = t % D_OUT;
    const float* xr = x + (size_t)i * C_IN;
    float acc = 0.f;
#pragma unroll 8
    for (int c = 0; c < C_IN; ++c) acc = fmaf(xr[c], W[c * D_OUT + d], acc);
    g_h[t] = acc + b[d];
}

// ---------------- 2) batchnorm stats (deterministic) ----------------
__global__ void k_stats() {
    __shared__ float ss[256];
    __shared__ float sq[256];
    int d = blockIdx.x;
    int tid = threadIdx.x;
    float s = 0.f, q = 0.f;
    for (int i = tid; i < N_NODES; i += 256) {
        float v = g_h[i * D_OUT + d];
        s += v;
        q = fmaf(v, v, q);
    }
    ss[tid] = s; sq[tid] = q;
    __syncthreads();
    for (int o = 128; o > 0; o >>= 1) {
        if (tid < o) { ss[tid] += ss[tid + o]; sq[tid] += sq[tid + o]; }
        __syncthreads();
    }
    if (tid == 0) {
        float mu = ss[0] / (float)N_NODES;
        float var = sq[0] / (float)N_NODES - mu * mu;
        g_mu[d] = mu;
        g_rinv[d] = 1.f / sqrtf(var + 1e-5f);
    }
}

// ---------------- 3) emb = relu(bn(h)); embn = emb + noise*1e-4 ----------------
__global__ void k_emb(const float* __restrict__ noise, const float* __restrict__ gamma,
                      const float* __restrict__ beta) {
    int t = blockIdx.x * blockDim.x + threadIdx.x;
    if (t >= N_NODES * D_OUT) return;
    int d = t % D_OUT;
    float e = (g_h[t] - g_mu[d]) * g_rinv[d] * gamma[d] + beta[d];
    e = fmaxf(e, 0.f);
    g_emb[t] = e;
    g_embn[t] = e + noise[t] * 1e-4f;
}

// ---------------- 4) row squared norms; build padded pos4 ----------------
// pos squared-norm mimics jnp.sum(pos*pos, axis=1): separately-rounded squares,
// left-to-right reduction, NO fma contraction (bit-match with reference).
__global__ void k_sqn(const float* __restrict__ pos) {
    int i = blockIdx.x * blockDim.x + threadIdx.x;
    if (i >= N_NODES) return;
    float s = 0.f;
#pragma unroll
    for (int d = 0; d < D_OUT; ++d) {
        float v = g_emb[i * D_OUT + d];
        s = fmaf(v, v, s);
    }
    g_sqe[i] = s;
    float p0 = pos[i * 3 + 0], p1 = pos[i * 3 + 1], p2 = pos[i * 3 + 2];
    float s0 = __fmul_rn(p0, p0);
    float s1 = __fmul_rn(p1, p1);
    float s2 = __fmul_rn(p2, p2);
    float psq = __fadd_rn(__fadd_rn(s0, s1), s2);
    g_pos4[i] = make_float4(p0, p1, p2, psq);
}

// ---------------- warp-distributed top-k insert ----------------
// List distributed: lane r (0..31) holds the r-th smallest (d2, idx); lanes
// >=16 are don't-care overflow (sentinels flow into them). kth (lane 15) is
// the selection threshold. All control flow is warp-uniform.
__device__ __forceinline__ bool lt_pair(float d2a, int ia, float d2b, int ib) {
    return (d2a < d2b) || (d2a == d2b && ia < ib);
}

__device__ __forceinline__ void warp_process_hits(
    unsigned mask, float d2, int jj, int lane,
    float& kd, int& ki, float& kth_d, int& kth_i) {
    while (mask) {
        int src = __ffs(mask) - 1;
        mask &= mask - 1;
        float dn = __shfl_sync(FULLM, d2, src);
        int   in = __shfl_sync(FULLM, jj, src);
        if (lt_pair(dn, in, kth_d, kth_i)) {        // recheck vs updated kth (uniform)
            bool p = lt_pair(dn, in, kd, ki);       // suffix of lanes shifts up
            unsigned pm = __ballot_sync(FULLM, p);
            int pos = __ffs(pm) - 1;
            float kdu = __shfl_up_sync(FULLM, kd, 1);
            int   kiu = __shfl_up_sync(FULLM, ki, 1);
            if (p) {
                kd = (lane == pos) ? dn : kdu;
                ki = (lane == pos) ? in : kiu;
            }
            kth_d = __shfl_sync(FULLM, kd, 15);
            kth_i = __shfl_sync(FULLM, ki, 15);
        }
    }
}

// ---------------- 5a) emb knn: warp per query ----------------
__global__ void __launch_bounds__(KNN_TPB) k_knn_emb(const float* __restrict__ feat,
                                                     const float* __restrict__ sqn,
                                                     int* __restrict__ out_idx) {
    __shared__ float s_feat[TC * EPAD];
    __shared__ float s_sq[TC];
    const int lane = threadIdx.x & 31;
    const int wid = threadIdx.x >> 5;
    const int q = blockIdx.x * WARPS_PB + wid;     // always < N_NODES (625*16)

    float qv[D_OUT];
#pragma unroll
    for (int d = 0; d < D_OUT; ++d) qv[d] = feat[(size_t)q * D_OUT + d];
    const float qsq = sqn[q];

    float kd = inf_f();  int ki = 0x7fffffff;
    float kth_d = inf_f(); int kth_i = 0x7fffffff;

    for (int base = 0; base < N_NODES; base += TC) {
        const int cnt = min(TC, N_NODES - base);
        __syncthreads();
        for (int idx = threadIdx.x; idx < cnt * D_OUT; idx += KNN_TPB) {
            int c = idx / D_OUT, d = idx - c * D_OUT;
            s_feat[c * EPAD + d] = feat[(size_t)(base + c) * D_OUT + d];
        }
        if (threadIdx.x < cnt) s_sq[threadIdx.x] = sqn[base + threadIdx.x];
        __syncthreads();

        for (int c0 = 0; c0 < cnt; c0 += 64) {
            const int ca = c0 + lane;
            const int cb = ca + 32;
            const int ja = base + ca;
            const int jb = base + cb;

            float a0 = 0.f, a1 = 0.f;
            const float2* ra = (const float2*)&s_feat[ca * EPAD];
            const float2* rb = (const float2*)&s_feat[(cb < TC ? cb : ca) * EPAD];
#pragma unroll
            for (int kk = 0; kk < D_OUT / 2; ++kk) {
                float2 va = ra[kk];
                float2 vb = rb[kk];
                a0 = fmaf(qv[2 * kk], va.x, a0);
                a0 = fmaf(qv[2 * kk + 1], va.y, a0);
                a1 = fmaf(qv[2 * kk], vb.x, a1);
                a1 = fmaf(qv[2 * kk + 1], vb.y, a1);
            }
            float d2a = fmaf(-2.f, a0, qsq + s_sq[ca < TC ? ca : 0]);
            float d2b = fmaf(-2.f, a1, qsq + s_sq[cb < TC ? cb : 0]);
            int jja = ja, jjb = jb;
            if (ca >= cnt || ja == q) { d2a = inf_f(); jja = 0x7fffffff; }
            if (cb >= cnt || jb == q) { d2b = inf_f(); jjb = 0x7fffffff; }

            unsigned m0 = __ballot_sync(FULLM, lt_pair(d2a, jja, kth_d, kth_i));
            unsigned m1 = __ballot_sync(FULLM, lt_pair(d2b, jjb, kth_d, kth_i));
            if (m0) warp_process_hits(m0, d2a, jja, lane, kd, ki, kth_d, kth_i);
            if (m1) warp_process_hits(m1, d2b, jjb, lane, kd, ki, kth_d, kth_i);
        }
    }
    if (lane < KNN_K) out_idx[q * KNN_K + lane] = ki;
}

// ---------------- 5b) pos knn: warp per query ----------------
__global__ void __launch_bounds__(KNN_TPB) k_knn_pos(const float4* __restrict__ p4,
                                                     int* __restrict__ out_idx) {
    __shared__ float4 s_p[TC];
    const int lane = threadIdx.x & 31;
    const int wid = threadIdx.x >> 5;
    const int q = blockIdx.x * WARPS_PB + wid;

    const float4 qp = p4[q];

    float kd = inf_f();  int ki = 0x7fffffff;
    float kth_d = inf_f(); int kth_i = 0x7fffffff;

    for (int base = 0; base < N_NODES; base += TC) {
        const int cnt = min(TC, N_NODES - base);
        __syncthreads();
        if (threadIdx.x < cnt) s_p[threadIdx.x] = p4[base + threadIdx.x];
        __syncthreads();

        for (int c0 = 0; c0 < cnt; c0 += 64) {
            const int ca = c0 + lane;
            const int cb = ca + 32;
            const int ja = base + ca;
            const int jb = base + cb;

            float4 va = s_p[ca < TC ? ca : 0];
            float4 vb = s_p[cb < TC ? cb : 0];
            // dot as ascending fma chain (matches reference GEMM rounding)
            float a0 = fmaf(qp.x, va.x, 0.f); a0 = fmaf(qp.y, va.y, a0); a0 = fmaf(qp.z, va.z, a0);
            float a1 = fmaf(qp.x, vb.x, 0.f); a1 = fmaf(qp.y, vb.y, a1); a1 = fmaf(qp.z, vb.z, a1);
            // d2 = fl( fl(sq_i + sq_j) - fl(2*dot) )   (bit-match reference)
            float d2a = __fadd_rn(__fadd_rn(qp.w, va.w), -__fmul_rn(2.f, a0));
            float d2b = __fadd_rn(__fadd_rn(qp.w, vb.w), -__fmul_rn(2.f, a1));
            int jja = ja, jjb = jb;
            if (ca >= cnt || ja == q) { d2a = inf_f(); jja = 0x7fffffff; }
            if (cb >= cnt || jb == q) { d2b = inf_f(); jjb = 0x7fffffff; }

            unsigned m0 = __ballot_sync(FULLM, lt_pair(d2a, jja, kth_d, kth_i));
            unsigned m1 = __ballot_sync(FULLM, lt_pair(d2b, jjb, kth_d, kth_i));
            if (m0) warp_process_hits(m0, d2a, jja, lane, kd, ki, kth_d, kth_i);
            if (m1) warp_process_hits(m1, d2b, jjb, lane, kd, ki, kth_d, kth_i);
        }
    }
    if (lane < KNN_K) out_idx[q * KNN_K + lane] = ki;
}

// ---------------- 7) epilogue: p, soft_index_v, edges_large, edge_index ----------------
__global__ void k_final(const float* __restrict__ tptr, float* __restrict__ out) {
    const int NK = N_NODES * KNN_K;
    int e = blockIdx.x * blockDim.x + threadIdx.x;
    if (e >= NK) return;
    int i = e / KNN_K;
    int src = g_idx_emb[e];
    float s = 0.f;
#pragma unroll
    for (int d = 0; d < D_OUT; ++d) {
        float df = g_embn[src * D_OUT + d] - g_embn[i * D_OUT + d];
        s = fmaf(df, df, s);
    }
    float dist = sqrtf(s);
    float p = expf(-tptr[0] * dist);
    float fi = (float)i;
    float fs = (float)src;

    out[e] = p;                               // p
    out[NK + e] = p;                          // soft_index_v row 0
    out[2 * NK + e] = fi;                     // soft_index_v row 1 (dst)
    out[3 * NK + e] = fs;                     // edges_large row 0 (src)
    out[4 * NK + e] = fi;                     // edges_large row 1 (dst)
    out[5 * NK + e] = fs;                     // edge_index row 0, emb part
    out[6 * NK + e] = (float)g_idx_pos[e];    // edge_index row 0, pos part
    out[7 * NK + e] = fi;                     // edge_index row 1, emb part
    out[8 * NK + e] = fi;                     // edge_index row 1, pos part
}

// ---------------- launch ----------------
extern "C" void kernel_launch(void* const* d_in, const int* in_sizes, int n_in,
                              void* d_out, int out_size) {
    const float* x     = (const float*)d_in[0];
    const float* pos   = (const float*)d_in[1];
    const float* noise = (const float*)d_in[2];
    const float* W     = (const float*)d_in[3];
    const float* b     = (const float*)d_in[4];
    const float* gamma = (const float*)d_in[5];
    const float* beta  = (const float*)d_in[6];
    const float* t     = (const float*)d_in[7];
    float* out = (float*)d_out;

    int nd = N_NODES * D_OUT;
    k_linear<<<(nd + 255) / 256, 256>>>(x, W, b);
    k_stats<<<D_OUT, 256>>>();
    k_emb<<<(nd + 255) / 256, 256>>>(noise, gamma, beta);
    k_sqn<<<(N_NODES + 255) / 256, 256>>>(pos);

    int* d_idx_emb; cudaGetSymbolAddress((void**)&d_idx_emb, g_idx_emb);
    int* d_idx_pos; cudaGetSymbolAddress((void**)&d_idx_pos, g_idx_pos);
    float* d_emb;   cudaGetSymbolAddress((void**)&d_emb, g_emb);
    float* d_sqe;   cudaGetSymbolAddress((void**)&d_sqe, g_sqe);
    float4* d_pos4; cudaGetSymbolAddress((void**)&d_pos4, g_pos4);

    const int nblk = N_NODES / WARPS_PB;   // 625
    k_knn_emb<<<nblk, KNN_TPB>>>(d_emb, d_sqe, d_idx_emb);
    k_knn_pos<<<nblk, KNN_TPB>>>(d_pos4, d_idx_pos);

    const int NK = N_NODES * KNN_K;
    k_final<<<(NK + 255) / 256, 256>>>(t, out);
    (void)in_sizes; (void)n_in; (void)out_size;
}